// round 3
// baseline (speedup 1.0000x reference)
#include <cuda_runtime.h>
#include <cuda_bf16.h>

// Problem shape (fixed per dataset problem)
#define BB 4
#define SS 2048
#define HH 1024

// ---------------- scratch (no allocations allowed) ----------------
__device__ float g_value[BB * SS * HH];   // 32 MB: value projection
__device__ float g_P[BB * SS * SS];       // 64 MB: softmax probabilities
__device__ float g_a[BB * SS];            // (X·U)/sqrt(64)
__device__ float g_c[BB * SS];            // (X·V)

// ---------------- kernel 1: rank-1 score vectors ----------------
// a[b,s] = (sum_h hs[b,s,h]*U[h] + U[H]) / 8
// c[b,s] =  sum_h hs[b,s,h]*V[h] + V[H]
__global__ __launch_bounds__(256) void compute_ac_kernel(
    const float* __restrict__ hs, const float* __restrict__ U,
    const float* __restrict__ V, float* __restrict__ a, float* __restrict__ c) {
    const int token = blockIdx.x;               // b*S + s
    const float* x = hs + (long)token * HH;
    const int tid = threadIdx.x;
    float su = 0.f, sv = 0.f;
    for (int h = tid; h < HH; h += 256) {
        float v = x[h];
        su = fmaf(v, U[h], su);
        sv = fmaf(v, V[h], sv);
    }
    __shared__ float rU[256], rV[256];
    rU[tid] = su; rV[tid] = sv;
    __syncthreads();
    for (int s = 128; s > 0; s >>= 1) {
        if (tid < s) { rU[tid] += rU[tid + s]; rV[tid] += rV[tid + s]; }
        __syncthreads();
    }
    if (tid == 0) {
        a[token] = (rU[0] + U[HH]) * 0.125f;   // fold 1/sqrt(HEAD_SIZE)=1/8
        c[token] = rV[0] + V[HH];
    }
}

// ---------------- kernel 2: per-row softmax -> P ----------------
// P[b,s,t] = softmax_t( a[b,s]*c[b,t] + mask[b,t] )
__global__ __launch_bounds__(256) void softmax_rows_kernel(
    const float* __restrict__ a, const float* __restrict__ c,
    const float* __restrict__ mask, float* __restrict__ P) {
    const int row = blockIdx.x;                 // b*S + s
    const int b = row >> 11;                    // row / S (S=2048)
    const float av = a[row];
    const float* cb = c + b * SS;
    const float* mb = mask + b * SS;
    float* Pr = P + (long)row * SS;
    const int tid = threadIdx.x;
    __shared__ float red[256];

    float mx = -3.4e38f;
    for (int t = tid; t < SS; t += 256)
        mx = fmaxf(mx, fmaf(av, cb[t], mb[t]));
    red[tid] = mx; __syncthreads();
    for (int s = 128; s > 0; s >>= 1) {
        if (tid < s) red[tid] = fmaxf(red[tid], red[tid + s]);
        __syncthreads();
    }
    mx = red[0]; __syncthreads();

    float sum = 0.f;
    for (int t = tid; t < SS; t += 256)
        sum += __expf(fmaf(av, cb[t], mb[t]) - mx);
    red[tid] = sum; __syncthreads();
    for (int s = 128; s > 0; s >>= 1) {
        if (tid < s) red[tid] += red[tid + s];
        __syncthreads();
    }
    const float invL = 1.0f / red[0];

    for (int t = tid; t < SS; t += 256)
        Pr[t] = __expf(fmaf(av, cb[t], mb[t]) - mx) * invL;
}

// ---------------- SGEMM: C = A @ B (+bias), 128x128x8 tiles, 8x8/thread ----
// BNT=true : B stored row-major [N,K]  (C[i,j] = sum_k A[i,k]*B[j,k])
// BNT=false: B stored row-major [K,N]  (C[i,j] = sum_k A[i,k]*B[k,j])
// All dims assumed multiples of tile sizes (holds: 8192/2048/1024).
constexpr int BM = 128, BN = 128, BK = 8, TM = 8, TN = 8;

template <bool BNT>
__global__ __launch_bounds__(256) void sgemm_kernel(
    const float* __restrict__ A, const float* __restrict__ Bm,
    const float* __restrict__ bias, float* __restrict__ C,
    int N, int K, long sA, long sB, long sC) {
    const int tid = threadIdx.x;
    A  += blockIdx.z * sA + (long)blockIdx.y * BM * K;
    Bm += blockIdx.z * sB;
    if (BNT) Bm += (long)blockIdx.x * BN * K;
    else     Bm += blockIdx.x * BN;
    C  += blockIdx.z * sC + (long)blockIdx.y * BM * N + blockIdx.x * BN;

    __shared__ float As[BK * BM];
    __shared__ float Bs[BK * BN];

    const int tCol = tid & 15;         // 0..15
    const int tRow = tid >> 4;         // 0..15
    const int lRow = tid >> 1;         // 0..127   (K-major loads)
    const int lCol = (tid & 1) * 4;    // 0 or 4
    const int bRow = tid >> 5;         // 0..7     (NN B loads)
    const int bCol = (tid & 31) * 4;   // 0..124

    float acc[TM][TN] = {};
    float rM[TM], rN[TN];

    for (int kt = 0; kt < K; kt += BK) {
        float4 a4 = *reinterpret_cast<const float4*>(A + (long)lRow * K + kt + lCol);
        As[(lCol + 0) * BM + lRow] = a4.x;
        As[(lCol + 1) * BM + lRow] = a4.y;
        As[(lCol + 2) * BM + lRow] = a4.z;
        As[(lCol + 3) * BM + lRow] = a4.w;
        if constexpr (BNT) {
            float4 b4 = *reinterpret_cast<const float4*>(Bm + (long)lRow * K + kt + lCol);
            Bs[(lCol + 0) * BN + lRow] = b4.x;
            Bs[(lCol + 1) * BN + lRow] = b4.y;
            Bs[(lCol + 2) * BN + lRow] = b4.z;
            Bs[(lCol + 3) * BN + lRow] = b4.w;
        } else {
            float4 b4 = *reinterpret_cast<const float4*>(Bm + (long)(kt + bRow) * N + bCol);
            *reinterpret_cast<float4*>(&Bs[bRow * BN + bCol]) = b4;
        }
        __syncthreads();

#pragma unroll
        for (int k = 0; k < BK; k++) {
#pragma unroll
            for (int i = 0; i < TM; i++) rM[i] = As[k * BM + tRow * TM + i];
#pragma unroll
            for (int j = 0; j < TN; j++) rN[j] = Bs[k * BN + tCol * TN + j];
#pragma unroll
            for (int i = 0; i < TM; i++)
#pragma unroll
                for (int j = 0; j < TN; j++)
                    acc[i][j] = fmaf(rM[i], rN[j], acc[i][j]);
        }
        __syncthreads();
    }

#pragma unroll
    for (int i = 0; i < TM; i++) {
        float* cr = C + (long)(tRow * TM + i) * N + tCol * TN;
#pragma unroll
        for (int j = 0; j < TN; j += 4) {
            float4 v;
            v.x = acc[i][j]; v.y = acc[i][j + 1];
            v.z = acc[i][j + 2]; v.w = acc[i][j + 3];
            if (bias) {
                const float* bb = bias + blockIdx.x * BN + tCol * TN + j;
                v.x += bb[0]; v.y += bb[1]; v.z += bb[2]; v.w += bb[3];
            }
            *reinterpret_cast<float4*>(cr + j) = v;
        }
    }
}

// ---------------- launch ----------------
extern "C" void kernel_launch(void* const* d_in, const int* in_sizes, int n_in,
                              void* d_out, int out_size) {
    const float* hs   = (const float*)d_in[0];   // [B,S,H]
    const float* mask = (const float*)d_in[1];   // [B,S]
    const float* W    = (const float*)d_in[2];   // [H,H]
    const float* bvec = (const float*)d_in[3];   // [H]
    const float* U    = (const float*)d_in[4];   // [H+1,1]
    const float* V    = (const float*)d_in[5];   // [1,H+1]
    float* out = (float*)d_out;                  // [B,S,H]

    float *d_value, *d_P, *d_a, *d_c;
    cudaGetSymbolAddress((void**)&d_value, g_value);
    cudaGetSymbolAddress((void**)&d_P, g_P);
    cudaGetSymbolAddress((void**)&d_a, g_a);
    cudaGetSymbolAddress((void**)&d_c, g_c);

    // 1) rank-1 score vectors a, c
    compute_ac_kernel<<<BB * SS, 256>>>(hs, U, V, d_a, d_c);

    // 2) value projection: g_value = hs @ W^T + b   (M=B*S, N=H, K=H, B is [N,K])
    {
        dim3 grid(HH / BN, (BB * SS) / BM, 1);
        sgemm_kernel<true><<<grid, 256>>>(hs, W, bvec, d_value, HH, HH, 0, 0, 0);
    }

    // 3) softmax rows -> P
    softmax_rows_kernel<<<BB * SS, 256>>>(d_a, d_c, mask, d_P);

    // 4) out = P @ value   (per batch: M=S, N=H, K=S, B is [K,N])
    {
        dim3 grid(HH / BN, SS / BM, BB);
        sgemm_kernel<false><<<grid, 256>>>(d_P, d_value, nullptr, out,
                                           HH, SS,
                                           (long)SS * SS, (long)SS * HH, (long)SS * HH);
    }
}

// round 5
// speedup vs baseline: 2.4563x; 2.4563x over previous
#include <cuda_runtime.h>
#include <cuda_bf16.h>
#include <cstdint>

// Problem shape (fixed per dataset problem)
#define BB 4
#define SS 2048
#define HH 1024

// ---------------- scratch (no allocations allowed) ----------------
__device__ float g_value[BB * SS * HH];   // 32 MB: value projection
__device__ float g_P[BB * SS * SS];       // 64 MB: softmax probabilities
__device__ float g_a[BB * SS];            // (X·U)/sqrt(64)
__device__ float g_c[BB * SS];            // (X·V)

__device__ __forceinline__ float to_tf32(float x) {
    uint32_t u;
    asm("cvt.rna.tf32.f32 %0, %1;" : "=r"(u) : "f"(x));
    return __uint_as_float(u);
}

__device__ __forceinline__ void mma_tf32(
    float& d0, float& d1, float& d2, float& d3,
    uint32_t a0, uint32_t a1, uint32_t a2, uint32_t a3,
    uint32_t b0, uint32_t b1) {
    asm volatile(
        "mma.sync.aligned.m16n8k8.row.col.f32.tf32.tf32.f32 "
        "{%0,%1,%2,%3}, {%4,%5,%6,%7}, {%8,%9}, {%0,%1,%2,%3};"
        : "+f"(d0), "+f"(d1), "+f"(d2), "+f"(d3)
        : "r"(a0), "r"(a1), "r"(a2), "r"(a3), "r"(b0), "r"(b1));
}

// ---------------- kernel 1: rank-1 score vectors ----------------
__global__ __launch_bounds__(256) void compute_ac_kernel(
    const float* __restrict__ hs, const float* __restrict__ U,
    const float* __restrict__ V, float* __restrict__ a, float* __restrict__ c) {
    const int token = blockIdx.x;               // b*S + s
    const float* x = hs + (long)token * HH;
    const int tid = threadIdx.x;
    float su = 0.f, sv = 0.f;
    for (int h = tid; h < HH; h += 256) {
        float v = x[h];
        su = fmaf(v, U[h], su);
        sv = fmaf(v, V[h], sv);
    }
    __shared__ float rU[256], rV[256];
    rU[tid] = su; rV[tid] = sv;
    __syncthreads();
    for (int s = 128; s > 0; s >>= 1) {
        if (tid < s) { rU[tid] += rU[tid + s]; rV[tid] += rV[tid + s]; }
        __syncthreads();
    }
    if (tid == 0) {
        a[token] = (rU[0] + U[HH]) * 0.125f;   // fold 1/sqrt(HEAD_SIZE)=1/8
        c[token] = rV[0] + V[HH];
    }
}

// ---------------- kernel 2: per-row softmax -> P ----------------
__global__ __launch_bounds__(256) void softmax_rows_kernel(
    const float* __restrict__ a, const float* __restrict__ c,
    const float* __restrict__ mask, float* __restrict__ P) {
    const int row = blockIdx.x;                 // b*S + s
    const int b = row >> 11;                    // row / S (S=2048)
    const float av = a[row];
    const float* cb = c + b * SS;
    const float* mb = mask + b * SS;
    float* Pr = P + (long)row * SS;
    const int tid = threadIdx.x;
    __shared__ float red[256];

    float mx = -3.4e38f;
    for (int t = tid; t < SS; t += 256)
        mx = fmaxf(mx, fmaf(av, cb[t], mb[t]));
    red[tid] = mx; __syncthreads();
    for (int s = 128; s > 0; s >>= 1) {
        if (tid < s) red[tid] = fmaxf(red[tid], red[tid + s]);
        __syncthreads();
    }
    mx = red[0]; __syncthreads();

    float sum = 0.f;
    for (int t = tid; t < SS; t += 256)
        sum += __expf(fmaf(av, cb[t], mb[t]) - mx);
    red[tid] = sum; __syncthreads();
    for (int s = 128; s > 0; s >>= 1) {
        if (tid < s) red[tid] += red[tid + s];
        __syncthreads();
    }
    const float invL = 1.0f / red[0];

    for (int t = tid; t < SS; t += 256)
        Pr[t] = __expf(fmaf(av, cb[t], mb[t]) - mx) * invL;
}

// ---------------- TF32 tensor-core GEMM: C = A @ B (+bias) ----------------
// BNT=true : B stored row-major [N,K]  (C[i,j] = sum_k A[i,k]*B[j,k])
// BNT=false: B stored row-major [K,N]  (C[i,j] = sum_k A[i,k]*B[k,j])
// Block tile 128x128x16, 8 warps (2x4), warp tile 64x32, mma m16n8k8.
// Shared layout: [row][k], row stride 20 (conflict-free fragment loads:
// bank(20n+k) covers all 32 banks for n in 0..7, k in 0..3).
constexpr int BM = 128, BN = 128, BK = 16;
constexpr int SSTR = 20;  // shared row stride (floats)

template <bool BNT>
__global__ __launch_bounds__(256) void tgemm_kernel(
    const float* __restrict__ A, const float* __restrict__ Bm,
    const float* __restrict__ bias, float* __restrict__ C,
    int N, int K, long sA, long sB, long sC) {
    const int tid = threadIdx.x;
    const int lane = tid & 31;
    const int wid = tid >> 5;
    const int warp_m = wid >> 2;        // 0..1  -> 64 rows
    const int warp_n = wid & 3;         // 0..3  -> 32 cols

    A  += blockIdx.z * sA + (long)blockIdx.y * BM * K;
    Bm += blockIdx.z * sB;
    if (BNT) Bm += (long)blockIdx.x * BN * K;
    else     Bm += blockIdx.x * BN;
    C  += blockIdx.z * sC + (long)blockIdx.y * BM * N + blockIdx.x * BN;

    __shared__ float As[BM * SSTR];     // [m][k]
    __shared__ float Bs[BN * SSTR];     // [n][k]

    float acc[4][4][4] = {};            // [mi][ni][frag]

    const int g = lane >> 2;            // 0..7
    const int q = lane & 3;             // 0..3

    for (int kt = 0; kt < K; kt += BK) {
        // --- load A tile: 128 rows x 16 k, 2 float4 per thread ---
#pragma unroll
        for (int i = 0; i < 2; i++) {
            int idx = tid + 256 * i;            // 0..511
            int row = idx >> 2;
            int k4 = (idx & 3) * 4;
            float4 v = *reinterpret_cast<const float4*>(A + (long)row * K + kt + k4);
            float* d = &As[row * SSTR + k4];
            d[0] = to_tf32(v.x); d[1] = to_tf32(v.y);
            d[2] = to_tf32(v.z); d[3] = to_tf32(v.w);
        }
        // --- load B tile into [n][k] ---
        if constexpr (BNT) {
#pragma unroll
            for (int i = 0; i < 2; i++) {
                int idx = tid + 256 * i;
                int row = idx >> 2;             // n
                int k4 = (idx & 3) * 4;
                float4 v = *reinterpret_cast<const float4*>(Bm + (long)row * K + kt + k4);
                float* d = &Bs[row * SSTR + k4];
                d[0] = to_tf32(v.x); d[1] = to_tf32(v.y);
                d[2] = to_tf32(v.z); d[3] = to_tf32(v.w);
            }
        } else {
            // B is [K,N]: 16 k-rows x 128 n, scalar loads (coalesced), transposed store
#pragma unroll
            for (int i = 0; i < 8; i++) {
                int e = tid + 256 * i;          // 0..2047
                int krow = e >> 7;              // 0..15
                int n = e & 127;
                Bs[n * SSTR + krow] = to_tf32(Bm[(long)(kt + krow) * N + n]);
            }
        }
        __syncthreads();

        // --- 2 k-steps of m16n8k8 ---
#pragma unroll
        for (int ks = 0; ks < BK; ks += 8) {
            uint32_t af[4][4], bf[4][2];
#pragma unroll
            for (int mi = 0; mi < 4; mi++) {
                const float* ap = &As[(warp_m * 64 + mi * 16 + g) * SSTR + ks + q];
                af[mi][0] = __float_as_uint(ap[0]);
                af[mi][1] = __float_as_uint(ap[8 * SSTR]);
                af[mi][2] = __float_as_uint(ap[4]);
                af[mi][3] = __float_as_uint(ap[8 * SSTR + 4]);
            }
#pragma unroll
            for (int ni = 0; ni < 4; ni++) {
                const float* bp = &Bs[(warp_n * 32 + ni * 8 + g) * SSTR + ks + q];
                bf[ni][0] = __float_as_uint(bp[0]);
                bf[ni][1] = __float_as_uint(bp[4]);
            }
#pragma unroll
            for (int mi = 0; mi < 4; mi++)
#pragma unroll
                for (int ni = 0; ni < 4; ni++)
                    mma_tf32(acc[mi][ni][0], acc[mi][ni][1],
                             acc[mi][ni][2], acc[mi][ni][3],
                             af[mi][0], af[mi][1], af[mi][2], af[mi][3],
                             bf[ni][0], bf[ni][1]);
        }
        __syncthreads();
    }

    // --- epilogue ---
    const float* bb = bias ? (bias + blockIdx.x * BN) : nullptr;
#pragma unroll
    for (int mi = 0; mi < 4; mi++) {
        int r0 = warp_m * 64 + mi * 16 + g;
#pragma unroll
        for (int ni = 0; ni < 4; ni++) {
            int c0 = warp_n * 32 + ni * 8 + q * 2;
            float b0 = 0.f, b1 = 0.f;
            if (bb) { b0 = bb[c0]; b1 = bb[c0 + 1]; }
            float2 v0 = make_float2(acc[mi][ni][0] + b0, acc[mi][ni][1] + b1);
            float2 v1 = make_float2(acc[mi][ni][2] + b0, acc[mi][ni][3] + b1);
            *reinterpret_cast<float2*>(C + (long)r0 * N + c0) = v0;
            *reinterpret_cast<float2*>(C + (long)(r0 + 8) * N + c0) = v1;
        }
    }
}

// ---------------- launch ----------------
extern "C" void kernel_launch(void* const* d_in, const int* in_sizes, int n_in,
                              void* d_out, int out_size) {
    const float* hs   = (const float*)d_in[0];   // [B,S,H]
    const float* mask = (const float*)d_in[1];   // [B,S]
    const float* W    = (const float*)d_in[2];   // [H,H]
    const float* bvec = (const float*)d_in[3];   // [H]
    const float* U    = (const float*)d_in[4];   // [H+1,1]
    const float* V    = (const float*)d_in[5];   // [1,H+1]
    float* out = (float*)d_out;                  // [B,S,H]

    float *d_value, *d_P, *d_a, *d_c;
    cudaGetSymbolAddress((void**)&d_value, g_value);
    cudaGetSymbolAddress((void**)&d_P, g_P);
    cudaGetSymbolAddress((void**)&d_a, g_a);
    cudaGetSymbolAddress((void**)&d_c, g_c);

    // 1) rank-1 score vectors a, c
    compute_ac_kernel<<<BB * SS, 256>>>(hs, U, V, d_a, d_c);

    // 2) value projection: g_value = hs @ W^T + b   (M=B*S, N=H, K=H, B is [N,K])
    {
        dim3 grid(HH / BN, (BB * SS) / BM, 1);
        tgemm_kernel<true><<<grid, 256>>>(hs, W, bvec, d_value, HH, HH, 0, 0, 0);
    }

    // 3) softmax rows -> P
    softmax_rows_kernel<<<BB * SS, 256>>>(d_a, d_c, mask, d_P);

    // 4) out = P @ value   (per batch: M=S, N=H, K=S, B is [K,N])
    {
        dim3 grid(HH / BN, SS / BM, BB);
        tgemm_kernel<false><<<grid, 256>>>(d_P, d_value, nullptr, out,
                                           HH, SS,
                                           (long)SS * SS, (long)SS * HH, (long)SS * HH);
    }
}

// round 13
// speedup vs baseline: 2.8124x; 1.1450x over previous
#include <cuda_runtime.h>
#include <cstdint>

// Problem shape (fixed per dataset problem)
#define BB 4
#define SS 2048
#define HH 1024

// ---------------- scratch (no allocations allowed) ----------------
__device__ float g_valueT[HH * BB * SS];  // 32 MB: value^T [h][b*S+s], tf32-rounded
__device__ float g_P[BB * SS * SS];       // 64 MB: softmax probs, tf32-rounded
__device__ float g_hsr[BB * SS * HH];     // 32 MB: hs rounded to tf32
__device__ float g_wr[HH * HH];           //  4 MB: W rounded to tf32
__device__ float g_a[BB * SS];
__device__ float g_c[BB * SS];

__device__ __forceinline__ float to_tf32(float x) {
    uint32_t u; asm("cvt.rna.tf32.f32 %0, %1;" : "=r"(u) : "f"(x));
    return __uint_as_float(u);
}

__device__ __forceinline__ void mma_tf32(
    float& d0, float& d1, float& d2, float& d3,
    uint32_t a0, uint32_t a1, uint32_t a2, uint32_t a3,
    uint32_t b0, uint32_t b1) {
    asm volatile(
        "mma.sync.aligned.m16n8k8.row.col.f32.tf32.tf32.f32 "
        "{%0,%1,%2,%3}, {%4,%5,%6,%7}, {%8,%9}, {%0,%1,%2,%3};"
        : "+f"(d0), "+f"(d1), "+f"(d2), "+f"(d3)
        : "r"(a0), "r"(a1), "r"(a2), "r"(a3), "r"(b0), "r"(b1));
}

#define CPA(dst, src) \
    asm volatile("cp.async.cg.shared.global [%0], [%1], 16;" :: "r"(dst), "l"(src))
#define CPC() asm volatile("cp.async.commit_group;")
#define CPW(n) asm volatile("cp.async.wait_group %0;" :: "n"(n))

// ---------------- tf32 rounding pass ----------------
__global__ __launch_bounds__(256) void cvt_kernel(
    const float4* __restrict__ src, float4* __restrict__ dst, int n4) {
    int i = blockIdx.x * 256 + threadIdx.x;
    if (i < n4) {
        float4 v = src[i];
        v.x = to_tf32(v.x); v.y = to_tf32(v.y);
        v.z = to_tf32(v.z); v.w = to_tf32(v.w);
        dst[i] = v;
    }
}

// ---------------- kernel 1: rank-1 score vectors ----------------
__global__ __launch_bounds__(256) void compute_ac_kernel(
    const float* __restrict__ hs, const float* __restrict__ U,
    const float* __restrict__ V, float* __restrict__ a, float* __restrict__ c) {
    const int token = blockIdx.x;
    const float* x = hs + (long)token * HH;
    const int tid = threadIdx.x;
    float su = 0.f, sv = 0.f;
    for (int h = tid; h < HH; h += 256) {
        float v = x[h];
        su = fmaf(v, U[h], su);
        sv = fmaf(v, V[h], sv);
    }
    __shared__ float rU[256], rV[256];
    rU[tid] = su; rV[tid] = sv;
    __syncthreads();
    for (int s = 128; s > 0; s >>= 1) {
        if (tid < s) { rU[tid] += rU[tid + s]; rV[tid] += rV[tid + s]; }
        __syncthreads();
    }
    if (tid == 0) {
        a[token] = (rU[0] + U[HH]) * 0.125f;
        c[token] = rV[0] + V[HH];
    }
}

// ---------------- kernel 2: per-row softmax -> P (tf32-rounded) -----------
__global__ __launch_bounds__(256) void softmax_rows_kernel(
    const float* __restrict__ a, const float* __restrict__ c,
    const float* __restrict__ mask, float* __restrict__ P) {
    const int row = blockIdx.x;
    const int b = row >> 11;
    const float av = a[row];
    const float* cb = c + b * SS;
    const float* mb = mask + b * SS;
    float* Pr = P + (long)row * SS;
    const int tid = threadIdx.x;
    __shared__ float red[256];

    float mx = -3.4e38f;
    for (int t = tid; t < SS; t += 256)
        mx = fmaxf(mx, fmaf(av, cb[t], mb[t]));
    red[tid] = mx; __syncthreads();
    for (int s = 128; s > 0; s >>= 1) {
        if (tid < s) red[tid] = fmaxf(red[tid], red[tid + s]);
        __syncthreads();
    }
    mx = red[0]; __syncthreads();

    float sum = 0.f;
    for (int t = tid; t < SS; t += 256)
        sum += __expf(fmaf(av, cb[t], mb[t]) - mx);
    red[tid] = sum; __syncthreads();
    for (int s = 128; s > 0; s >>= 1) {
        if (tid < s) red[tid] += red[tid + s];
        __syncthreads();
    }
    const float invL = 1.0f / red[0];

    for (int t = tid; t < SS; t += 256)
        Pr[t] = to_tf32(__expf(fmaf(av, cb[t], mb[t]) - mx) * invL);
}

// ---------------- pipelined TT tf32 GEMM: C = A @ B^T ----------------
// A: [M][lda] K-major rows (tf32 bits). B: [N][ldb] K-major rows (tf32 bits).
// Block 128x128, BK=16, 4-stage cp.async pipeline, 8 warps (2x4), warp 64x32.
// SMEM layout per operand row: 16 floats = 4 chunks of 16B; chunk c stored at
// c ^ ((r&3)^((r>>2)&1)) -> conflict-free mma fragment loads.
// TRANSOUT=true : C[n*ldc + m] = to_tf32(acc + bias[n])   (value^T)
// TRANSOUT=false: C[z*sCz + m*ldc + n] = acc              (attention out)
constexpr int BM = 128, BN = 128, BK = 16, STAGES = 4;
constexpr int STAGE_WORDS = (BM + BN) * BK;        // 4096 words = 16 KB
constexpr int SMEM_BYTES = STAGES * STAGE_WORDS * 4;  // 64 KB

template <bool TRANSOUT>
__global__ __launch_bounds__(256, 2) void tgemm_pipe(
    const float* __restrict__ A, const float* __restrict__ B,
    const float* __restrict__ bias, float* __restrict__ C,
    long lda, long ldb, long ldc, long sAz, long sBz, long sCz, int K) {
    extern __shared__ float sm[];
    const uint32_t sbase = (uint32_t)__cvta_generic_to_shared(sm);
    const int tid = threadIdx.x, lane = tid & 31, wid = tid >> 5;
    const int warp_m = wid >> 2, warp_n = wid & 3;
    const int g = lane >> 2, q = lane & 3;

    A += blockIdx.z * sAz + (long)blockIdx.y * BM * lda;
    B += blockIdx.z * sBz + (long)blockIdx.x * BN * ldb;

    // fill mapping: thread -> row tid>>1, chunk base (tid&1)*2 (+0,+1)
    const int fr = tid >> 1;
    const int fc = (tid & 1) * 2;
    const int fsw = (fr & 3) ^ ((fr >> 2) & 1);
    const uint32_t aoff = fr * 64;
    const uint32_t boff = BM * 64 + fr * 64;

    auto fill = [&](int stage, int kt) {
        const uint32_t sb = sbase + stage * (STAGE_WORDS * 4);
        const float* ga = A + (long)fr * lda + kt + fc * 4;
        CPA(sb + aoff + (((fc)     ^ fsw) << 4), ga);
        CPA(sb + aoff + (((fc + 1) ^ fsw) << 4), ga + 4);
        const float* gb = B + (long)fr * ldb + kt + fc * 4;
        CPA(sb + boff + (((fc)     ^ fsw) << 4), gb);
        CPA(sb + boff + (((fc + 1) ^ fsw) << 4), gb + 4);
    };

    const int NT = K >> 4;
#pragma unroll
    for (int t = 0; t < STAGES - 1; t++) {
        if (t < NT) fill(t, t << 4);
        CPC();
    }

    float acc[4][4][4] = {};
    const int s = (g & 3) ^ ((g >> 2) & 1);

    for (int t = 0; t < NT; t++) {
        CPW(STAGES - 2);
        __syncthreads();
        const int pf = t + STAGES - 1;
        if (pf < NT) fill(pf & (STAGES - 1), pf << 4);
        CPC();

        const uint32_t* As = (const uint32_t*)sm + (t & (STAGES - 1)) * STAGE_WORDS;
        const uint32_t* Bs = As + BM * 16;
#pragma unroll
        for (int ks = 0; ks < 2; ks++) {
            const int c0 = ks * 2;
            const int o0 = (((c0)     ^ s) << 2) + q;
            const int o1 = (((c0 + 1) ^ s) << 2) + q;
            uint32_t af[4][4], bf[4][2];
#pragma unroll
            for (int mi = 0; mi < 4; mi++) {
                const int r = (warp_m * 64 + mi * 16 + g) * 16;
                af[mi][0] = As[r + o0];
                af[mi][1] = As[r + 128 + o0];   // +8 rows
                af[mi][2] = As[r + o1];
                af[mi][3] = As[r + 128 + o1];
            }
#pragma unroll
            for (int ni = 0; ni < 4; ni++) {
                const int r = (warp_n * 32 + ni * 8 + g) * 16;
                bf[ni][0] = Bs[r + o0];
                bf[ni][1] = Bs[r + o1];
            }
#pragma unroll
            for (int mi = 0; mi < 4; mi++)
#pragma unroll
                for (int ni = 0; ni < 4; ni++)
                    mma_tf32(acc[mi][ni][0], acc[mi][ni][1],
                             acc[mi][ni][2], acc[mi][ni][3],
                             af[mi][0], af[mi][1], af[mi][2], af[mi][3],
                             bf[ni][0], bf[ni][1]);
        }
    }

    // ---------------- epilogue ----------------
    if (TRANSOUT) {
#pragma unroll
        for (int mi = 0; mi < 4; mi++) {
            const long m0 = (long)blockIdx.y * BM + warp_m * 64 + mi * 16 + g;
#pragma unroll
            for (int ni = 0; ni < 4; ni++) {
                const int n0 = blockIdx.x * BN + warp_n * 32 + ni * 8 + q * 2;
                const float b0 = bias[n0], b1 = bias[n0 + 1];
                C[(long)n0 * ldc + m0]           = to_tf32(acc[mi][ni][0] + b0);
                C[(long)(n0 + 1) * ldc + m0]     = to_tf32(acc[mi][ni][1] + b1);
                C[(long)n0 * ldc + m0 + 8]       = to_tf32(acc[mi][ni][2] + b0);
                C[(long)(n0 + 1) * ldc + m0 + 8] = to_tf32(acc[mi][ni][3] + b1);
            }
        }
    } else {
        float* Cz = C + blockIdx.z * sCz + (long)blockIdx.y * BM * ldc + blockIdx.x * BN;
#pragma unroll
        for (int mi = 0; mi < 4; mi++) {
            const int r0 = warp_m * 64 + mi * 16 + g;
#pragma unroll
            for (int ni = 0; ni < 4; ni++) {
                const int c0 = warp_n * 32 + ni * 8 + q * 2;
                *reinterpret_cast<float2*>(Cz + (long)r0 * ldc + c0) =
                    make_float2(acc[mi][ni][0], acc[mi][ni][1]);
                *reinterpret_cast<float2*>(Cz + (long)(r0 + 8) * ldc + c0) =
                    make_float2(acc[mi][ni][2], acc[mi][ni][3]);
            }
        }
    }
}

// ---------------- launch ----------------
extern "C" void kernel_launch(void* const* d_in, const int* in_sizes, int n_in,
                              void* d_out, int out_size) {
    const float* hs   = (const float*)d_in[0];   // [B,S,H]
    const float* mask = (const float*)d_in[1];   // [B,S]
    const float* W    = (const float*)d_in[2];   // [H,H]
    const float* bvec = (const float*)d_in[3];   // [H]
    const float* U    = (const float*)d_in[4];   // [H+1,1]
    const float* V    = (const float*)d_in[5];   // [1,H+1]
    float* out = (float*)d_out;                  // [B,S,H]

    float *d_valueT, *d_P, *d_a, *d_c, *d_hsr, *d_wr;
    cudaGetSymbolAddress((void**)&d_valueT, g_valueT);
    cudaGetSymbolAddress((void**)&d_P, g_P);
    cudaGetSymbolAddress((void**)&d_a, g_a);
    cudaGetSymbolAddress((void**)&d_c, g_c);
    cudaGetSymbolAddress((void**)&d_hsr, g_hsr);
    cudaGetSymbolAddress((void**)&d_wr, g_wr);

    cudaFuncSetAttribute(tgemm_pipe<true>,
                         cudaFuncAttributeMaxDynamicSharedMemorySize, SMEM_BYTES);
    cudaFuncSetAttribute(tgemm_pipe<false>,
                         cudaFuncAttributeMaxDynamicSharedMemorySize, SMEM_BYTES);

    // 0) round hs, W to tf32 once
    cvt_kernel<<<(BB * SS * HH / 4 + 255) / 256, 256>>>(
        (const float4*)hs, (float4*)d_hsr, BB * SS * HH / 4);
    cvt_kernel<<<(HH * HH / 4 + 255) / 256, 256>>>(
        (const float4*)W, (float4*)d_wr, HH * HH / 4);

    // 1) rank-1 score vectors a, c
    compute_ac_kernel<<<BB * SS, 256>>>(hs, U, V, d_a, d_c);

    // 2) value^T = (hs @ W^T + b)^T : A=hsr [8192,1024], B=Wr [1024,1024]
    {
        dim3 grid(HH / BN, (BB * SS) / BM, 1);
        tgemm_pipe<true><<<grid, 256, SMEM_BYTES>>>(
            d_hsr, d_wr, bvec, d_valueT,
            HH, HH, (long)BB * SS, 0, 0, 0, HH);
    }

    // 3) softmax rows -> P (tf32-rounded)
    softmax_rows_kernel<<<BB * SS, 256>>>(d_a, d_c, mask, d_P);

    // 4) out = P @ value : A=P [S,S] per batch, B=value^T [H][B*S]
    {
        dim3 grid(HH / BN, SS / BM, BB);
        tgemm_pipe<false><<<grid, 256, SMEM_BYTES>>>(
            d_P, d_valueT, nullptr, out,
            SS, (long)BB * SS, HH,
            (long)SS * SS, SS, (long)SS * HH, SS);
    }
}

// round 14
// speedup vs baseline: 3.3153x; 1.1788x over previous
#include <cuda_runtime.h>
#include <cstdint>

// Problem shape (fixed per dataset problem)
#define BB 4
#define SS 2048
#define HH 1024

// ---------------- scratch (no allocations allowed) ----------------
__device__ float g_valueT[HH * BB * SS];  // 32 MB: value^T [h][b*S+s], tf32-rounded
__device__ float g_P[BB * SS * SS];       // 64 MB: softmax probs, tf32-rounded
__device__ float g_hsr[BB * SS * HH];     // 32 MB: hs rounded to tf32
__device__ float g_wr[HH * HH];           //  4 MB: W rounded to tf32
__device__ float g_a[BB * SS];
__device__ float g_c[BB * SS];

__device__ __forceinline__ float to_tf32(float x) {
    uint32_t u; asm("cvt.rna.tf32.f32 %0, %1;" : "=r"(u) : "f"(x));
    return __uint_as_float(u);
}

__device__ __forceinline__ void mma_tf32(
    float& d0, float& d1, float& d2, float& d3,
    uint32_t a0, uint32_t a1, uint32_t a2, uint32_t a3,
    uint32_t b0, uint32_t b1) {
    asm volatile(
        "mma.sync.aligned.m16n8k8.row.col.f32.tf32.tf32.f32 "
        "{%0,%1,%2,%3}, {%4,%5,%6,%7}, {%8,%9}, {%0,%1,%2,%3};"
        : "+f"(d0), "+f"(d1), "+f"(d2), "+f"(d3)
        : "r"(a0), "r"(a1), "r"(a2), "r"(a3), "r"(b0), "r"(b1));
}

__device__ __forceinline__ void ldsm4(uint32_t& r0, uint32_t& r1,
                                      uint32_t& r2, uint32_t& r3, uint32_t addr) {
    asm volatile("ldmatrix.sync.aligned.m8n8.x4.shared.b16 {%0,%1,%2,%3}, [%4];"
                 : "=r"(r0), "=r"(r1), "=r"(r2), "=r"(r3) : "r"(addr));
}

#define CPA(dst, src) \
    asm volatile("cp.async.cg.shared.global [%0], [%1], 16;" :: "r"(dst), "l"(src))
#define CPC() asm volatile("cp.async.commit_group;")
#define CPW(n) asm volatile("cp.async.wait_group %0;" :: "n"(n))

// ---------------- tf32 rounding pass ----------------
__global__ __launch_bounds__(256) void cvt_kernel(
    const float4* __restrict__ src, float4* __restrict__ dst, int n4) {
    int i = blockIdx.x * 256 + threadIdx.x;
    if (i < n4) {
        float4 v = src[i];
        v.x = to_tf32(v.x); v.y = to_tf32(v.y);
        v.z = to_tf32(v.z); v.w = to_tf32(v.w);
        dst[i] = v;
    }
}

// ---------------- kernel 1: rank-1 score vectors ----------------
__global__ __launch_bounds__(256) void compute_ac_kernel(
    const float* __restrict__ hs, const float* __restrict__ U,
    const float* __restrict__ V, float* __restrict__ a, float* __restrict__ c) {
    const int token = blockIdx.x;
    const float* x = hs + (long)token * HH;
    const int tid = threadIdx.x;
    float su = 0.f, sv = 0.f;
    for (int h = tid; h < HH; h += 256) {
        float v = x[h];
        su = fmaf(v, U[h], su);
        sv = fmaf(v, V[h], sv);
    }
    __shared__ float rU[256], rV[256];
    rU[tid] = su; rV[tid] = sv;
    __syncthreads();
    for (int s = 128; s > 0; s >>= 1) {
        if (tid < s) { rU[tid] += rU[tid + s]; rV[tid] += rV[tid + s]; }
        __syncthreads();
    }
    if (tid == 0) {
        a[token] = (rU[0] + U[HH]) * 0.125f;
        c[token] = rV[0] + V[HH];
    }
}

// ---------------- kernel 2: per-row softmax -> P (tf32-rounded) -----------
__global__ __launch_bounds__(256) void softmax_rows_kernel(
    const float* __restrict__ a, const float* __restrict__ c,
    const float* __restrict__ mask, float* __restrict__ P) {
    const int row = blockIdx.x;
    const int b = row >> 11;
    const float av = a[row];
    const float* cb = c + b * SS;
    const float* mb = mask + b * SS;
    float* Pr = P + (long)row * SS;
    const int tid = threadIdx.x;
    __shared__ float red[256];

    float mx = -3.4e38f;
    for (int t = tid; t < SS; t += 256)
        mx = fmaxf(mx, fmaf(av, cb[t], mb[t]));
    red[tid] = mx; __syncthreads();
    for (int s = 128; s > 0; s >>= 1) {
        if (tid < s) red[tid] = fmaxf(red[tid], red[tid + s]);
        __syncthreads();
    }
    mx = red[0]; __syncthreads();

    float sum = 0.f;
    for (int t = tid; t < SS; t += 256)
        sum += __expf(fmaf(av, cb[t], mb[t]) - mx);
    red[tid] = sum; __syncthreads();
    for (int s = 128; s > 0; s >>= 1) {
        if (tid < s) red[tid] += red[tid + s];
        __syncthreads();
    }
    const float invL = 1.0f / red[0];

    for (int t = tid; t < SS; t += 256)
        Pr[t] = to_tf32(__expf(fmaf(av, cb[t], mb[t]) - mx) * invL);
}

// ---------------- pipelined TT tf32 GEMM: C = A @ B^T ----------------
// A: [M][lda] K-major rows (tf32 bits). B: [N][ldb] K-major rows (tf32 bits).
// Block 128x128, BK=16, 4-stage cp.async pipeline, 8 warps (2x4), warp 64x32.
// SMEM row = 16 floats = 4 chunks of 16B; chunk c stored at c ^ sw(r),
// sw(r) = (r&3)^((r>>2)&1). Fragments fed via ldmatrix.x4 (conflict-free).
// TRANSOUT=true : C[n*ldc + m] = to_tf32(acc + bias[n])   (value^T, smem transpose)
// TRANSOUT=false: C[z*sCz + m*ldc + n] = acc              (attention out)
constexpr int BM = 128, BN = 128, BK = 16, STAGES = 4;
constexpr int STAGE_BYTES = (BM + BN) * BK * 4;       // 16 KB
constexpr int SMEM_BYTES = 128 * 129 * 4;             // 66048 >= 4*16KB pipeline

template <bool TRANSOUT>
__global__ __launch_bounds__(256, 2) void tgemm_pipe(
    const float* __restrict__ A, const float* __restrict__ B,
    const float* __restrict__ bias, float* __restrict__ C,
    long lda, long ldb, long ldc, long sAz, long sBz, long sCz, int K) {
    extern __shared__ float sm[];
    const uint32_t sbase = (uint32_t)__cvta_generic_to_shared(sm);
    const int tid = threadIdx.x, lane = tid & 31, wid = tid >> 5;
    const int warp_m = wid >> 2, warp_n = wid & 3;
    const int g = lane >> 2, q = lane & 3;

    A += blockIdx.z * sAz + (long)blockIdx.y * BM * lda;
    B += blockIdx.z * sBz + (long)blockIdx.x * BN * ldb;

    // ---- cp.async fill mapping: thread -> row tid>>1, chunk base (tid&1)*2 ----
    const int fr = tid >> 1;
    const int fc = (tid & 1) * 2;
    const int fsw = (fr & 3) ^ ((fr >> 2) & 1);
    const uint32_t aoff = fr * 64;
    const uint32_t boff = BM * 64 + fr * 64;

    auto fill = [&](int stage, int kt) {
        const uint32_t sb = sbase + stage * STAGE_BYTES;
        const float* ga = A + (long)fr * lda + kt + fc * 4;
        CPA(sb + aoff + (((fc)     ^ fsw) << 4), ga);
        CPA(sb + aoff + (((fc + 1) ^ fsw) << 4), ga + 4);
        const float* gb = B + (long)fr * ldb + kt + fc * 4;
        CPA(sb + boff + (((fc)     ^ fsw) << 4), gb);
        CPA(sb + boff + (((fc + 1) ^ fsw) << 4), gb + 4);
    };

    // ---- ldmatrix per-lane address constants ----
    // lane -> e=lane&7; sw is lane-constant: (lane&3)^((lane>>2)&1) of e bits
    const int e = lane & 7;
    const int swl = (e & 3) ^ ((e >> 2) & 1);
    const int mA = lane >> 4;          // A: matrix pair -> chunk select
    const int mB = (lane >> 3) & 1;    // B: matrix parity -> chunk select
    const uint32_t abase = (uint32_t)(warp_m * 64 + ((lane >> 3) & 1) * 8 + e) * 64;
    const uint32_t bbase = (uint32_t)(BM * 64) +
                           (uint32_t)(warp_n * 32 + (lane >> 4) * 8 + e) * 64;
    const uint32_t ckA0 = (uint32_t)(((0 + mA) ^ swl) << 4);
    const uint32_t ckA1 = (uint32_t)(((2 + mA) ^ swl) << 4);
    const uint32_t ckB0 = (uint32_t)(((0 + mB) ^ swl) << 4);
    const uint32_t ckB1 = (uint32_t)(((2 + mB) ^ swl) << 4);

    const int NT = K >> 4;
#pragma unroll
    for (int t = 0; t < STAGES - 1; t++) {
        if (t < NT) fill(t, t << 4);
        CPC();
    }

    float acc[4][4][4] = {};

    for (int t = 0; t < NT; t++) {
        CPW(STAGES - 2);
        __syncthreads();
        const int pf = t + STAGES - 1;
        if (pf < NT) fill(pf & (STAGES - 1), pf << 4);
        CPC();

        const uint32_t su = sbase + (t & (STAGES - 1)) * STAGE_BYTES;
#pragma unroll
        for (int ks = 0; ks < 2; ks++) {
            const uint32_t cka = ks ? ckA1 : ckA0;
            const uint32_t ckb = ks ? ckB1 : ckB0;
            uint32_t af[4][4], bf[4][2];
#pragma unroll
            for (int mi = 0; mi < 4; mi++)
                ldsm4(af[mi][0], af[mi][1], af[mi][2], af[mi][3],
                      su + abase + mi * 1024 + cka);
#pragma unroll
            for (int p = 0; p < 2; p++)
                ldsm4(bf[2 * p][0], bf[2 * p][1], bf[2 * p + 1][0], bf[2 * p + 1][1],
                      su + bbase + p * 1024 + ckb);
#pragma unroll
            for (int mi = 0; mi < 4; mi++)
#pragma unroll
                for (int ni = 0; ni < 4; ni++)
                    mma_tf32(acc[mi][ni][0], acc[mi][ni][1],
                             acc[mi][ni][2], acc[mi][ni][3],
                             af[mi][0], af[mi][1], af[mi][2], af[mi][3],
                             bf[ni][0], bf[ni][1]);
        }
    }

    // ---------------- epilogue ----------------
    if (TRANSOUT) {
        // transpose through smem (reuse pipeline buffer), then coalesced stores
        CPW(0);
        __syncthreads();
#pragma unroll
        for (int mi = 0; mi < 4; mi++) {
            const int m0 = warp_m * 64 + mi * 16 + g;
#pragma unroll
            for (int ni = 0; ni < 4; ni++) {
                const int n0 = warp_n * 32 + ni * 8 + q * 2;
                sm[m0 * 129 + n0]           = acc[mi][ni][0];
                sm[m0 * 129 + n0 + 1]       = acc[mi][ni][1];
                sm[(m0 + 8) * 129 + n0]     = acc[mi][ni][2];
                sm[(m0 + 8) * 129 + n0 + 1] = acc[mi][ni][3];
            }
        }
        __syncthreads();
        const int n = tid >> 1;                 // 0..127
        const int mh = (tid & 1) * 64;          // m half
        const long ng = (long)blockIdx.x * BN + n;
        const float bn = bias[ng];
        float* cp = C + ng * ldc + (long)blockIdx.y * BM + mh;
#pragma unroll
        for (int j = 0; j < 64; j += 4) {
            float4 v;
            v.x = to_tf32(sm[(mh + j)     * 129 + n] + bn);
            v.y = to_tf32(sm[(mh + j + 1) * 129 + n] + bn);
            v.z = to_tf32(sm[(mh + j + 2) * 129 + n] + bn);
            v.w = to_tf32(sm[(mh + j + 3) * 129 + n] + bn);
            *reinterpret_cast<float4*>(cp + j) = v;
        }
    } else {
        float* Cz = C + blockIdx.z * sCz + (long)blockIdx.y * BM * ldc + blockIdx.x * BN;
#pragma unroll
        for (int mi = 0; mi < 4; mi++) {
            const int r0 = warp_m * 64 + mi * 16 + g;
#pragma unroll
            for (int ni = 0; ni < 4; ni++) {
                const int c0 = warp_n * 32 + ni * 8 + q * 2;
                *reinterpret_cast<float2*>(Cz + (long)r0 * ldc + c0) =
                    make_float2(acc[mi][ni][0], acc[mi][ni][1]);
                *reinterpret_cast<float2*>(Cz + (long)(r0 + 8) * ldc + c0) =
                    make_float2(acc[mi][ni][2], acc[mi][ni][3]);
            }
        }
    }
}

// ---------------- launch ----------------
extern "C" void kernel_launch(void* const* d_in, const int* in_sizes, int n_in,
                              void* d_out, int out_size) {
    const float* hs   = (const float*)d_in[0];   // [B,S,H]
    const float* mask = (const float*)d_in[1];   // [B,S]
    const float* W    = (const float*)d_in[2];   // [H,H]
    const float* bvec = (const float*)d_in[3];   // [H]
    const float* U    = (const float*)d_in[4];   // [H+1,1]
    const float* V    = (const float*)d_in[5];   // [1,H+1]
    float* out = (float*)d_out;                  // [B,S,H]

    float *d_valueT, *d_P, *d_a, *d_c, *d_hsr, *d_wr;
    cudaGetSymbolAddress((void**)&d_valueT, g_valueT);
    cudaGetSymbolAddress((void**)&d_P, g_P);
    cudaGetSymbolAddress((void**)&d_a, g_a);
    cudaGetSymbolAddress((void**)&d_c, g_c);
    cudaGetSymbolAddress((void**)&d_hsr, g_hsr);
    cudaGetSymbolAddress((void**)&d_wr, g_wr);

    cudaFuncSetAttribute(tgemm_pipe<true>,
                         cudaFuncAttributeMaxDynamicSharedMemorySize, SMEM_BYTES);
    cudaFuncSetAttribute(tgemm_pipe<false>,
                         cudaFuncAttributeMaxDynamicSharedMemorySize, SMEM_BYTES);

    // 0) round hs, W to tf32 once
    cvt_kernel<<<(BB * SS * HH / 4 + 255) / 256, 256>>>(
        (const float4*)hs, (float4*)d_hsr, BB * SS * HH / 4);
    cvt_kernel<<<(HH * HH / 4 + 255) / 256, 256>>>(
        (const float4*)W, (float4*)d_wr, HH * HH / 4);

    // 1) rank-1 score vectors a, c
    compute_ac_kernel<<<BB * SS, 256>>>(hs, U, V, d_a, d_c);

    // 2) value^T = (hs @ W^T + b)^T : A=hsr [8192,1024], B=Wr [1024,1024]
    {
        dim3 grid(HH / BN, (BB * SS) / BM, 1);
        tgemm_pipe<true><<<grid, 256, SMEM_BYTES>>>(
            d_hsr, d_wr, bvec, d_valueT,
            HH, HH, (long)BB * SS, 0, 0, 0, HH);
    }

    // 3) softmax rows -> P (tf32-rounded)
    softmax_rows_kernel<<<BB * SS, 256>>>(d_a, d_c, mask, d_P);

    // 4) out = P @ value : A=P [S,S] per batch, B=value^T [H][B*S]
    {
        dim3 grid(HH / BN, SS / BM, BB);
        tgemm_pipe<false><<<grid, 256, SMEM_BYTES>>>(
            d_P, d_valueT, nullptr, out,
            SS, (long)BB * SS, HH,
            (long)SS * SS, SS, (long)SS * HH, SS);
    }
}

// round 15
// speedup vs baseline: 5.3863x; 1.6247x over previous
#include <cuda_runtime.h>
#include <cuda_fp16.h>
#include <cstdint>

// Problem shape (fixed per dataset problem)
#define BB 4
#define SS 2048
#define HH 1024

// ---------------- scratch (no allocations allowed) ----------------
__device__ __half g_valueT[HH * BB * SS];  // 16 MB: value^T [h][b*S+s]
__device__ __half g_P[BB * SS * SS];       // 32 MB: softmax probs
__device__ __half g_hsh[BB * SS * HH];     // 16 MB: hs in fp16
__device__ __half g_wh[HH * HH];           //  2 MB: W in fp16
__device__ float g_a[BB * SS];
__device__ float g_c[BB * SS];

__device__ __forceinline__ void mma_f16(
    float& d0, float& d1, float& d2, float& d3,
    uint32_t a0, uint32_t a1, uint32_t a2, uint32_t a3,
    uint32_t b0, uint32_t b1) {
    asm volatile(
        "mma.sync.aligned.m16n8k16.row.col.f32.f16.f16.f32 "
        "{%0,%1,%2,%3}, {%4,%5,%6,%7}, {%8,%9}, {%0,%1,%2,%3};"
        : "+f"(d0), "+f"(d1), "+f"(d2), "+f"(d3)
        : "r"(a0), "r"(a1), "r"(a2), "r"(a3), "r"(b0), "r"(b1));
}

__device__ __forceinline__ void ldsm4(uint32_t& r0, uint32_t& r1,
                                      uint32_t& r2, uint32_t& r3, uint32_t addr) {
    asm volatile("ldmatrix.sync.aligned.m8n8.x4.shared.b16 {%0,%1,%2,%3}, [%4];"
                 : "=r"(r0), "=r"(r1), "=r"(r2), "=r"(r3) : "r"(addr));
}

#define CPA(dst, src) \
    asm volatile("cp.async.cg.shared.global [%0], [%1], 16;" :: "r"(dst), "l"(src))
#define CPC() asm volatile("cp.async.commit_group;")
#define CPW(n) asm volatile("cp.async.wait_group %0;" :: "n"(n))

// ---------------- fp32 -> fp16 conversion pass ----------------
__global__ __launch_bounds__(256) void cvt_h_kernel(
    const float4* __restrict__ src, uint2* __restrict__ dst, int n4) {
    int i = blockIdx.x * 256 + threadIdx.x;
    if (i < n4) {
        float4 v = src[i];
        __half2 h0 = __floats2half2_rn(v.x, v.y);
        __half2 h1 = __floats2half2_rn(v.z, v.w);
        uint2 u;
        u.x = *reinterpret_cast<uint32_t*>(&h0);
        u.y = *reinterpret_cast<uint32_t*>(&h1);
        dst[i] = u;
    }
}

// ---------------- kernel 1: rank-1 score vectors ----------------
__global__ __launch_bounds__(256) void compute_ac_kernel(
    const float* __restrict__ hs, const float* __restrict__ U,
    const float* __restrict__ V, float* __restrict__ a, float* __restrict__ c) {
    const int token = blockIdx.x;
    const float* x = hs + (long)token * HH;
    const int tid = threadIdx.x;
    float su = 0.f, sv = 0.f;
    for (int h = tid; h < HH; h += 256) {
        float v = x[h];
        su = fmaf(v, U[h], su);
        sv = fmaf(v, V[h], sv);
    }
    __shared__ float rU[256], rV[256];
    rU[tid] = su; rV[tid] = sv;
    __syncthreads();
    for (int s = 128; s > 0; s >>= 1) {
        if (tid < s) { rU[tid] += rU[tid + s]; rV[tid] += rV[tid + s]; }
        __syncthreads();
    }
    if (tid == 0) {
        a[token] = (rU[0] + U[HH]) * 0.125f;
        c[token] = rV[0] + V[HH];
    }
}

// ---------------- kernel 2: per-row softmax -> P (fp16) -----------
__global__ __launch_bounds__(256) void softmax_rows_kernel(
    const float* __restrict__ a, const float* __restrict__ c,
    const float* __restrict__ mask, __half* __restrict__ P) {
    const int row = blockIdx.x;
    const int b = row >> 11;
    const float av = a[row];
    const float* cb = c + b * SS;
    const float* mb = mask + b * SS;
    __half* Pr = P + (long)row * SS;
    const int tid = threadIdx.x;
    __shared__ float red[256];

    float mx = -3.4e38f;
    for (int t = tid; t < SS; t += 256)
        mx = fmaxf(mx, fmaf(av, cb[t], mb[t]));
    red[tid] = mx; __syncthreads();
    for (int s = 128; s > 0; s >>= 1) {
        if (tid < s) red[tid] = fmaxf(red[tid], red[tid + s]);
        __syncthreads();
    }
    mx = red[0]; __syncthreads();

    float sum = 0.f;
    for (int t = tid; t < SS; t += 256)
        sum += __expf(fmaf(av, cb[t], mb[t]) - mx);
    red[tid] = sum; __syncthreads();
    for (int s = 128; s > 0; s >>= 1) {
        if (tid < s) red[tid] += red[tid + s];
        __syncthreads();
    }
    const float invL = 1.0f / red[0];

    for (int t = tid; t < SS; t += 256)
        Pr[t] = __float2half_rn(__expf(fmaf(av, cb[t], mb[t]) - mx) * invL);
}

// ---------------- pipelined TT fp16 GEMM: C = A @ B^T ----------------
// A: [M][lda] half, K-major rows. B: [N][ldb] half, K-major rows.
// Block 128x128, BK=32 halves (64B rows), 4-stage cp.async pipeline,
// 8 warps (2x4), warp 64x32, mma m16n8k16 fp16 -> fp32 accum.
// SMEM row = 4 chunks of 16B; chunk c at c ^ sw(r), sw(r)=(r&3)^((r>>2)&1).
// Fragments via ldmatrix.x4 (conflict-free per 8-row phase).
// TRANSOUT=true : Ch[n*ldc + m] = half(acc + bias[n])  (value^T, smem transpose)
// TRANSOUT=false: Cf[z*sCz + m*ldc + n] = acc          (attention out, fp32)
constexpr int BM = 128, BN = 128, BK = 32, STAGES = 4;
constexpr int STAGE_BYTES = (BM + BN) * BK * 2;       // 16 KB
constexpr int SMEM_BYTES = 128 * 129 * 4;             // 66048 >= 4*16KB pipeline

template <bool TRANSOUT>
__global__ __launch_bounds__(256, 2) void hgemm_pipe(
    const __half* __restrict__ A, const __half* __restrict__ B,
    const float* __restrict__ bias, void* __restrict__ Cv,
    long lda, long ldb, long ldc, long sAz, long sBz, long sCz, int K) {
    extern __shared__ float sm[];
    const uint32_t sbase = (uint32_t)__cvta_generic_to_shared(sm);
    const int tid = threadIdx.x, lane = tid & 31, wid = tid >> 5;
    const int warp_m = wid >> 2, warp_n = wid & 3;
    const int g = lane >> 2, q = lane & 3;

    A += blockIdx.z * sAz + (long)blockIdx.y * BM * lda;
    B += blockIdx.z * sBz + (long)blockIdx.x * BN * ldb;

    // ---- cp.async fill: thread -> row tid>>1, chunk base (tid&1)*2 ----
    const int fr = tid >> 1;
    const int fc = (tid & 1) * 2;
    const int fsw = (fr & 3) ^ ((fr >> 2) & 1);
    const uint32_t aoff = fr * 64;
    const uint32_t boff = BM * 64 + fr * 64;

    auto fill = [&](int stage, int kt) {
        const uint32_t sb = sbase + stage * STAGE_BYTES;
        const __half* ga = A + (long)fr * lda + kt + fc * 8;
        CPA(sb + aoff + (((fc)     ^ fsw) << 4), ga);
        CPA(sb + aoff + (((fc + 1) ^ fsw) << 4), ga + 8);
        const __half* gb = B + (long)fr * ldb + kt + fc * 8;
        CPA(sb + boff + (((fc)     ^ fsw) << 4), gb);
        CPA(sb + boff + (((fc + 1) ^ fsw) << 4), gb + 8);
    };

    // ---- ldmatrix per-lane constants ----
    const int e = lane & 7;
    const int swl = (e & 3) ^ ((e >> 2) & 1);
    // A: lanes 0-7 -> (rows+0, k0-7), 8-15 -> (rows+8, k0-7),
    //    16-23 -> (rows+0, k8-15), 24-31 -> (rows+8, k8-15)
    const int rselA = (lane >> 3) & 1;
    const int cselA = lane >> 4;
    const uint32_t aRowOff = (uint32_t)(warp_m * 64 + rselA * 8 + e) * 64;
    const uint32_t ckA0 = (uint32_t)(((0 + cselA) ^ swl) << 4);
    const uint32_t ckA1 = (uint32_t)(((2 + cselA) ^ swl) << 4);
    // B: lanes 0-7 -> (n+0, k0-7), 8-15 -> (n+0, k8-15),
    //    16-23 -> (n+8, k0-7), 24-31 -> (n+8, k8-15)
    const int cselB = (lane >> 3) & 1;
    const int nselB = (lane >> 4) & 1;
    const uint32_t bRowOff = (uint32_t)(BM * 64) +
                             (uint32_t)(warp_n * 32 + nselB * 8 + e) * 64;
    const uint32_t ckB0 = (uint32_t)(((0 + cselB) ^ swl) << 4);
    const uint32_t ckB1 = (uint32_t)(((2 + cselB) ^ swl) << 4);

    const int NT = K >> 5;
#pragma unroll
    for (int t = 0; t < STAGES - 1; t++) {
        if (t < NT) fill(t, t << 5);
        CPC();
    }

    float acc[4][4][4] = {};

    for (int t = 0; t < NT; t++) {
        CPW(STAGES - 2);
        __syncthreads();
        const int pf = t + STAGES - 1;
        if (pf < NT) fill(pf & (STAGES - 1), pf << 5);
        CPC();

        const uint32_t su = sbase + (t & (STAGES - 1)) * STAGE_BYTES;
#pragma unroll
        for (int ks = 0; ks < 2; ks++) {
            const uint32_t cka = ks ? ckA1 : ckA0;
            const uint32_t ckb = ks ? ckB1 : ckB0;
            uint32_t af[4][4], bf[4][2];
#pragma unroll
            for (int mi = 0; mi < 4; mi++)
                ldsm4(af[mi][0], af[mi][1], af[mi][2], af[mi][3],
                      su + aRowOff + mi * 1024 + cka);
#pragma unroll
            for (int p = 0; p < 2; p++)
                ldsm4(bf[2 * p][0], bf[2 * p][1], bf[2 * p + 1][0], bf[2 * p + 1][1],
                      su + bRowOff + p * 1024 + ckb);
#pragma unroll
            for (int mi = 0; mi < 4; mi++)
#pragma unroll
                for (int ni = 0; ni < 4; ni++)
                    mma_f16(acc[mi][ni][0], acc[mi][ni][1],
                            acc[mi][ni][2], acc[mi][ni][3],
                            af[mi][0], af[mi][1], af[mi][2], af[mi][3],
                            bf[ni][0], bf[ni][1]);
        }
    }

    // ---------------- epilogue ----------------
    if (TRANSOUT) {
        __half* Ch = (__half*)Cv;
        // transpose through smem (reuse pipeline buffer), coalesced half stores
        CPW(0);
        __syncthreads();
#pragma unroll
        for (int mi = 0; mi < 4; mi++) {
            const int m0 = warp_m * 64 + mi * 16 + g;
#pragma unroll
            for (int ni = 0; ni < 4; ni++) {
                const int n0 = warp_n * 32 + ni * 8 + q * 2;
                sm[m0 * 129 + n0]           = acc[mi][ni][0];
                sm[m0 * 129 + n0 + 1]       = acc[mi][ni][1];
                sm[(m0 + 8) * 129 + n0]     = acc[mi][ni][2];
                sm[(m0 + 8) * 129 + n0 + 1] = acc[mi][ni][3];
            }
        }
        __syncthreads();
        const int n = tid >> 1;                 // 0..127
        const int mh = (tid & 1) * 64;          // m half
        const long ng = (long)blockIdx.x * BN + n;
        const float bn = bias[ng];
        __half* cp = Ch + ng * ldc + (long)blockIdx.y * BM + mh;
#pragma unroll
        for (int j = 0; j < 64; j += 8) {
            __half2 h[4];
#pragma unroll
            for (int p2 = 0; p2 < 4; p2++)
                h[p2] = __floats2half2_rn(
                    sm[(mh + j + 2 * p2)     * 129 + n] + bn,
                    sm[(mh + j + 2 * p2 + 1) * 129 + n] + bn);
            *reinterpret_cast<uint4*>(cp + j) = *reinterpret_cast<uint4*>(h);
        }
    } else {
        float* Cf = (float*)Cv + blockIdx.z * sCz +
                    (long)blockIdx.y * BM * ldc + blockIdx.x * BN;
#pragma unroll
        for (int mi = 0; mi < 4; mi++) {
            const int r0 = warp_m * 64 + mi * 16 + g;
#pragma unroll
            for (int ni = 0; ni < 4; ni++) {
                const int c0 = warp_n * 32 + ni * 8 + q * 2;
                *reinterpret_cast<float2*>(Cf + (long)r0 * ldc + c0) =
                    make_float2(acc[mi][ni][0], acc[mi][ni][1]);
                *reinterpret_cast<float2*>(Cf + (long)(r0 + 8) * ldc + c0) =
                    make_float2(acc[mi][ni][2], acc[mi][ni][3]);
            }
        }
    }
}

// ---------------- launch ----------------
extern "C" void kernel_launch(void* const* d_in, const int* in_sizes, int n_in,
                              void* d_out, int out_size) {
    const float* hs   = (const float*)d_in[0];   // [B,S,H]
    const float* mask = (const float*)d_in[1];   // [B,S]
    const float* W    = (const float*)d_in[2];   // [H,H]
    const float* bvec = (const float*)d_in[3];   // [H]
    const float* U    = (const float*)d_in[4];   // [H+1,1]
    const float* V    = (const float*)d_in[5];   // [1,H+1]
    float* out = (float*)d_out;                  // [B,S,H]

    __half *d_valueT, *d_P, *d_hsh, *d_wh;
    float *d_a, *d_c;
    cudaGetSymbolAddress((void**)&d_valueT, g_valueT);
    cudaGetSymbolAddress((void**)&d_P, g_P);
    cudaGetSymbolAddress((void**)&d_a, g_a);
    cudaGetSymbolAddress((void**)&d_c, g_c);
    cudaGetSymbolAddress((void**)&d_hsh, g_hsh);
    cudaGetSymbolAddress((void**)&d_wh, g_wh);

    cudaFuncSetAttribute(hgemm_pipe<true>,
                         cudaFuncAttributeMaxDynamicSharedMemorySize, SMEM_BYTES);
    cudaFuncSetAttribute(hgemm_pipe<false>,
                         cudaFuncAttributeMaxDynamicSharedMemorySize, SMEM_BYTES);

    // 0) convert hs, W to fp16 once
    cvt_h_kernel<<<(BB * SS * HH / 4 + 255) / 256, 256>>>(
        (const float4*)hs, (uint2*)d_hsh, BB * SS * HH / 4);
    cvt_h_kernel<<<(HH * HH / 4 + 255) / 256, 256>>>(
        (const float4*)W, (uint2*)d_wh, HH * HH / 4);

    // 1) rank-1 score vectors a, c (fp32 inputs)
    compute_ac_kernel<<<BB * SS, 256>>>(hs, U, V, d_a, d_c);

    // 2) value^T = (hs @ W^T + b)^T : A=hsh [8192,1024], B=Wh [1024,1024]
    {
        dim3 grid(HH / BN, (BB * SS) / BM, 1);
        hgemm_pipe<true><<<grid, 256, SMEM_BYTES>>>(
            d_hsh, d_wh, bvec, d_valueT,
            HH, HH, (long)BB * SS, 0, 0, 0, HH);
    }

    // 3) softmax rows -> P (fp16)
    softmax_rows_kernel<<<BB * SS, 256>>>(d_a, d_c, mask, d_P);

    // 4) out = P @ value : A=P [S,S] per batch, B=value^T [H][B*S]
    {
        dim3 grid(HH / BN, SS / BM, BB);
        hgemm_pipe<false><<<grid, 256, SMEM_BYTES>>>(
            d_P, d_valueT, nullptr, out,
            SS, (long)BB * SS, HH,
            (long)SS * SS, SS, (long)SS * HH, SS);
    }
}